// round 15
// baseline (speedup 1.0000x reference)
#include <cuda_runtime.h>
#include <cuda_bf16.h>

#define DD   768
#define BB   8
#define SS   2048
#define MTOT (BB * SS)
#define BK   32
#define PITCH 40                        // bf16 per smem row (80B, conflict-free)
#define STAGE_BYTES (128 * PITCH * 2)   // 10240 per operand tile
#define NSTAGE 3
#define ALPHA 0.036084391824351615f     // 1/sqrt(768)
#define KSPL 4                          // MT GEMM K-splits

typedef unsigned int u32;

// ---------------------------------------------------------------------------
// Device scratch (no allocations allowed)
// ---------------------------------------------------------------------------
__device__ __nv_bfloat16 g_xn [(size_t)MTOT * DD];      // LN output (bf16)
__device__ __nv_bfloat16 g_wqT[(size_t)DD * DD];        // Wq^T bf16 [i][m]
__device__ __nv_bfloat16 g_wkT[(size_t)DD * DD];        // Wk^T bf16 [j][m]
__device__ __nv_bfloat16 g_mt [(size_t)DD * DD];        // M^T bf16, MT[j][i]=M[i][j]
__device__ float         g_mtp[(size_t)KSPL * DD * DD]; // MT split-K fp32 partials
__device__ __nv_bfloat16 g_g  [(size_t)MTOT * DD];      // G = xn @ M  bf16
__device__ __nv_bfloat16 g_pb [(size_t)BB * SS * SS];   // p_unnorm = exp(logit) bf16
__device__ __nv_bfloat16 g_xt [(size_t)BB * DD * SS];   // x^T bf16 [b][d][s]
__device__ float         g_w  [DD];                     // w = Wk^T bq
__device__ float         g_c  [MTOT];                   // c_row = xn_row . w
__device__ float         g_ps [(size_t)MTOT * 16];      // per-(row, ntile) partial sums
__device__ float         g_si [MTOT];                   // 1 / row sum

// ---------------------------------------------------------------------------
__device__ __forceinline__ u32 smem_u32(const void* p) {
    u32 a;
    asm("{ .reg .u64 t; cvta.to.shared.u64 t, %1; cvt.u32.u64 %0, t; }" : "=r"(a) : "l"(p));
    return a;
}
#define CP_ASYNC16(sa, ga) \
    asm volatile("cp.async.cg.shared.global [%0], [%1], 16;" :: "r"(sa), "l"(ga) : "memory")
#define CP_COMMIT()  asm volatile("cp.async.commit_group;" ::: "memory")
#define CP_WAIT(n)   asm volatile("cp.async.wait_group %0;" :: "n"(n) : "memory")
#define LDSM_X4(r0, r1, r2, r3, addr) \
    asm volatile("ldmatrix.sync.aligned.m8n8.x4.shared.b16 {%0,%1,%2,%3}, [%4];" \
        : "=r"(r0), "=r"(r1), "=r"(r2), "=r"(r3) : "r"(addr))

__device__ __forceinline__ void mma16816(float* c, const u32* a, u32 b0, u32 b1) {
    asm volatile(
        "mma.sync.aligned.m16n8k16.row.col.f32.bf16.bf16.f32 "
        "{%0,%1,%2,%3}, {%4,%5,%6,%7}, {%8,%9}, {%0,%1,%2,%3};"
        : "+f"(c[0]), "+f"(c[1]), "+f"(c[2]), "+f"(c[3])
        : "r"(a[0]), "r"(a[1]), "r"(a[2]), "r"(a[3]), "r"(b0), "r"(b1));
}

// ---------------------------------------------------------------------------
// HMMA GEMM (R10-proven shape): C[m,n] = sum_{k<Kloop} A[m,k]*B[n,k]
// 128x128 CTA tile, 256 thr = 8 warps (4m x 2n), warp tile 32x64, BK=32,
// 3-stage cp.async, ldmatrix.x4, 1 sync/iter.
// MODE 0: bf16 out plain                                         (G)
// MODE 1: p=exp((v+c[col])*ALPHA) bf16 + per-row partial sums    (scores)
// MODE 2: fp32 out: v * g_si[row] + resid                        (av)
// MODE 4: fp32 out plain (split-K partials)                      (MT)
// ---------------------------------------------------------------------------
template <int MODE>
__global__ __launch_bounds__(256) void mma_gemm(
    const __nv_bfloat16* __restrict__ A, const __nv_bfloat16* __restrict__ B,
    void* __restrict__ Cv,
    const float* __restrict__ extra,       // MODE1: c vec (per batch); MODE2: resid
    int N, int K, int Kloop, long aStride, long bStride, long cStride)
{
    extern __shared__ char smem[];
    const u32 aTile0 = smem_u32(smem);
    const u32 bTile0 = aTile0 + NSTAGE * STAGE_BYTES;

    const int tid = threadIdx.x;
    const int wid = tid >> 5, lane = tid & 31;
    const int wm = wid & 3, wn = wid >> 2;          // 4 x 2 warp grid
    const int g = lane >> 2, t = lane & 3;          // mma fragment coords
    const int m0 = blockIdx.y * 128, n0 = blockIdx.x * 128;
    const int z = blockIdx.z;

    A += (size_t)z * aStride + (size_t)m0 * K;
    B += (size_t)z * bStride + (size_t)n0 * K;

    const int NC = Kloop / BK;
    const int r0 = tid >> 2, c0 = (tid & 3) * 8;
    const int r1 = r0 + 64;
    const u32 sA0 = aTile0 + r0 * (PITCH * 2) + c0 * 2;
    const u32 sA1 = aTile0 + r1 * (PITCH * 2) + c0 * 2;
    const u32 sB0 = bTile0 + r0 * (PITCH * 2) + c0 * 2;
    const u32 sB1 = bTile0 + r1 * (PITCH * 2) + c0 * 2;

    const int lr = lane & 15, lk = (lane >> 4) * 8;
    const u32 aLds = aTile0 + (wm * 32 + lr) * (PITCH * 2) + lk * 2;
    const u32 bLds = bTile0 + (wn * 64 + lr) * (PITCH * 2) + lk * 2;

    float acc[2][8][4];
    #pragma unroll
    for (int mt = 0; mt < 2; mt++)
        #pragma unroll
        for (int nt = 0; nt < 8; nt++)
            #pragma unroll
            for (int i = 0; i < 4; i++) acc[mt][nt][i] = 0.f;

    #pragma unroll
    for (int s = 0; s < 2; s++) {
        const __nv_bfloat16* Ak = A + (size_t)s * BK;
        const __nv_bfloat16* Bk = B + (size_t)s * BK;
        const u32 so = s * STAGE_BYTES;
        CP_ASYNC16(sA0 + so, Ak + (size_t)r0 * K + c0);
        CP_ASYNC16(sA1 + so, Ak + (size_t)r1 * K + c0);
        CP_ASYNC16(sB0 + so, Bk + (size_t)r0 * K + c0);
        CP_ASYNC16(sB1 + so, Bk + (size_t)r1 * K + c0);
        CP_COMMIT();
    }

    int st = 0;
    for (int c = 0; c < NC; ++c) {
        CP_WAIT(1);
        __syncthreads();

        if (c + 2 < NC) {
            const int ps = (st + 2 >= NSTAGE) ? st + 2 - NSTAGE : st + 2;
            const __nv_bfloat16* Ak = A + (size_t)(c + 2) * BK;
            const __nv_bfloat16* Bk = B + (size_t)(c + 2) * BK;
            const u32 so = ps * STAGE_BYTES;
            CP_ASYNC16(sA0 + so, Ak + (size_t)r0 * K + c0);
            CP_ASYNC16(sA1 + so, Ak + (size_t)r1 * K + c0);
            CP_ASYNC16(sB0 + so, Bk + (size_t)r0 * K + c0);
            CP_ASYNC16(sB1 + so, Bk + (size_t)r1 * K + c0);
        }
        CP_COMMIT();

        const u32 so = st * STAGE_BYTES;
        #pragma unroll
        for (int kk = 0; kk < 2; kk++) {
            u32 a[2][4], b[4][4];
            #pragma unroll
            for (int mt = 0; mt < 2; mt++)
                LDSM_X4(a[mt][0], a[mt][1], a[mt][2], a[mt][3],
                        aLds + so + mt * (16 * PITCH * 2) + kk * 32);
            #pragma unroll
            for (int np = 0; np < 4; np++)
                LDSM_X4(b[np][0], b[np][1], b[np][2], b[np][3],
                        bLds + so + np * (16 * PITCH * 2) + kk * 32);
            // b[np] = { b_{2np}[0], b_{2np+1}[0], b_{2np}[1], b_{2np+1}[1] }
            #pragma unroll
            for (int mt = 0; mt < 2; mt++)
                #pragma unroll
                for (int nt = 0; nt < 8; nt++)
                    mma16816(acc[mt][nt], a[mt], b[nt >> 1][nt & 1], b[nt >> 1][2 + (nt & 1)]);
        }
        st = (st + 1 >= NSTAGE) ? 0 : st + 1;
    }

    // Epilogue
    if (MODE == 0) {
        #pragma unroll
        for (int mt = 0; mt < 2; mt++)
            #pragma unroll
            for (int nt = 0; nt < 8; nt++) {
                const int row = m0 + wm * 32 + mt * 16 + g;
                const int col = n0 + wn * 64 + nt * 8 + 2 * t;
                __nv_bfloat16* Cb = (__nv_bfloat16*)Cv + (size_t)z * cStride;
                *(__nv_bfloat162*)(Cb + (size_t)row * N + col) =
                    __floats2bfloat162_rn(acc[mt][nt][0], acc[mt][nt][1]);
                *(__nv_bfloat162*)(Cb + (size_t)(row + 8) * N + col) =
                    __floats2bfloat162_rn(acc[mt][nt][2], acc[mt][nt][3]);
            }
    } else if (MODE == 4) {
        #pragma unroll
        for (int mt = 0; mt < 2; mt++)
            #pragma unroll
            for (int nt = 0; nt < 8; nt++) {
                const int row = m0 + wm * 32 + mt * 16 + g;
                const int col = n0 + wn * 64 + nt * 8 + 2 * t;
                float* Cf = (float*)Cv + (size_t)z * cStride;
                *(float2*)(Cf + (size_t)row * N + col) =
                    make_float2(acc[mt][nt][0], acc[mt][nt][1]);
                *(float2*)(Cf + (size_t)(row + 8) * N + col) =
                    make_float2(acc[mt][nt][2], acc[mt][nt][3]);
            }
    } else if (MODE == 1) {
        float rs[2][2] = {{0.f, 0.f}, {0.f, 0.f}};   // [mt][row half]
        const float* cv = extra + (size_t)z * SS;
        #pragma unroll
        for (int mt = 0; mt < 2; mt++)
            #pragma unroll
            for (int nt = 0; nt < 8; nt++) {
                const int row = m0 + wm * 32 + mt * 16 + g;
                const int col = n0 + wn * 64 + nt * 8 + 2 * t;
                float ca = cv[col], cb = cv[col + 1];
                float e0 = __expf((acc[mt][nt][0] + ca) * ALPHA);
                float e1 = __expf((acc[mt][nt][1] + cb) * ALPHA);
                float e2 = __expf((acc[mt][nt][2] + ca) * ALPHA);
                float e3 = __expf((acc[mt][nt][3] + cb) * ALPHA);
                rs[mt][0] += e0 + e1;
                rs[mt][1] += e2 + e3;
                __nv_bfloat16* Cb = (__nv_bfloat16*)Cv + (size_t)z * cStride;
                *(__nv_bfloat162*)(Cb + (size_t)row * N + col) = __floats2bfloat162_rn(e0, e1);
                *(__nv_bfloat162*)(Cb + (size_t)(row + 8) * N + col) = __floats2bfloat162_rn(e2, e3);
            }
        #pragma unroll
        for (int mt = 0; mt < 2; mt++)
            #pragma unroll
            for (int h = 0; h < 2; h++) {
                rs[mt][h] += __shfl_xor_sync(0xffffffffu, rs[mt][h], 1);
                rs[mt][h] += __shfl_xor_sync(0xffffffffu, rs[mt][h], 2);
            }
        __syncthreads();                      // done with mainloop smem; reuse
        float* sRow = (float*)smem;           // [128 rows][2 wn]
        if (t == 0) {
            #pragma unroll
            for (int mt = 0; mt < 2; mt++) {
                sRow[(wm * 32 + mt * 16 + g) * 2 + wn]     = rs[mt][0];
                sRow[(wm * 32 + mt * 16 + 8 + g) * 2 + wn] = rs[mt][1];
            }
        }
        __syncthreads();
        if (tid < 128) {
            float s = sRow[tid * 2] + sRow[tid * 2 + 1];
            g_ps[((size_t)z * SS + m0 + tid) * 16 + blockIdx.x] = s;
        }
    } else {
        float invs[2][2];
        #pragma unroll
        for (int mt = 0; mt < 2; mt++) {
            const int row = m0 + wm * 32 + mt * 16 + g;
            invs[mt][0] = g_si[(size_t)z * SS + row];
            invs[mt][1] = g_si[(size_t)z * SS + row + 8];
        }
        #pragma unroll
        for (int mt = 0; mt < 2; mt++)
            #pragma unroll
            for (int nt = 0; nt < 8; nt++) {
                const int row = m0 + wm * 32 + mt * 16 + g;
                const int col = n0 + wn * 64 + nt * 8 + 2 * t;
                float* Cf = (float*)Cv + (size_t)z * cStride;
                const float* R = extra + (size_t)z * cStride;
                float2 ra = *(const float2*)(R + (size_t)row * N + col);
                float2 rb = *(const float2*)(R + (size_t)(row + 8) * N + col);
                float v0 = acc[mt][nt][0] * invs[mt][0] + ra.x;
                float v1 = acc[mt][nt][1] * invs[mt][0] + ra.y;
                float v2 = acc[mt][nt][2] * invs[mt][1] + rb.x;
                float v3 = acc[mt][nt][3] * invs[mt][1] + rb.y;
                *(float2*)(Cf + (size_t)row * N + col) = make_float2(v0, v1);
                *(float2*)(Cf + (size_t)(row + 8) * N + col) = make_float2(v2, v3);
            }
    }
}

// ---------------------------------------------------------------------------
// Reductions
// ---------------------------------------------------------------------------
__device__ __forceinline__ float blockReduceSum(float v) {
    __shared__ float sh[32];
    int lane = threadIdx.x & 31, wid = threadIdx.x >> 5;
    #pragma unroll
    for (int o = 16; o; o >>= 1) v += __shfl_down_sync(0xffffffffu, v, o);
    if (lane == 0) sh[wid] = v;
    __syncthreads();
    float r = (threadIdx.x < (blockDim.x >> 5)) ? sh[threadIdx.x] : 0.f;
    if (wid == 0) {
        #pragma unroll
        for (int o = 16; o; o >>= 1) r += __shfl_down_sync(0xffffffffu, r, o);
        if (lane == 0) sh[0] = r;
    }
    __syncthreads();
    float out = sh[0];
    __syncthreads();
    return out;
}

// w[d] = sum_j bq[j] * Wk[j,d]
__global__ __launch_bounds__(256) void w_kernel(const float* __restrict__ Wk,
                                                const float* __restrict__ bq) {
    int d = blockIdx.x, t = threadIdx.x;
    float s = 0.f;
    for (int j = t; j < DD; j += 256) s += bq[j] * Wk[(size_t)j * DD + d];
    s = blockReduceSum(s);
    if (t == 0) g_w[d] = s;
}

// LayerNorm -> bf16, plus c_row = xn_row . w   (192 thr, float4 I/O)
__global__ __launch_bounds__(192) void ln_kernel(const float* __restrict__ x,
                                                 const float* __restrict__ g,
                                                 const float* __restrict__ b) {
    int row = blockIdx.x, t = threadIdx.x;
    float4 v = ((const float4*)(x + (size_t)row * DD))[t];
    float mean = blockReduceSum(v.x + v.y + v.z + v.w) * (1.0f / DD);
    float dx = v.x - mean, dy = v.y - mean, dz = v.z - mean, dw = v.w - mean;
    float q = dx * dx + dy * dy + dz * dz + dw * dw;
    float inv = rsqrtf(blockReduceSum(q) * (1.0f / DD) + 1e-5f);
    float4 gv = ((const float4*)g)[t];
    float4 bv = ((const float4*)b)[t];
    float4 wv = ((const float4*)g_w)[t];
    float x0 = dx * inv * gv.x + bv.x;
    float x1 = dy * inv * gv.y + bv.y;
    float x2 = dz * inv * gv.z + bv.z;
    float x3 = dw * inv * gv.w + bv.w;
    __nv_bfloat162 p0 = __floats2bfloat162_rn(x0, x1);
    __nv_bfloat162 p1 = __floats2bfloat162_rn(x2, x3);
    uint2 pk; pk.x = *(u32*)&p0; pk.y = *(u32*)&p1;
    *(uint2*)(g_xn + (size_t)row * DD + t * 4) = pk;
    float cdot = blockReduceSum(x0 * wv.x + x1 * wv.y + x2 * wv.z + x3 * wv.w);
    if (t == 0) g_c[row] = cdot;
}

// Transpose W fp32 [m][i] -> bf16 [i][m] for both weights
__global__ __launch_bounds__(256) void convwT_kernel(const float* __restrict__ Wq,
                                                     const float* __restrict__ Wk) {
    __shared__ float tq[32][33];
    __shared__ float tk[32][33];
    int m0 = blockIdx.x * 32, i0 = blockIdx.y * 32;
    int tx = threadIdx.x & 31, ty = threadIdx.x >> 5;
    #pragma unroll
    for (int r = 0; r < 4; r++) {
        tq[ty + r * 8][tx] = Wq[(size_t)(m0 + ty + r * 8) * DD + i0 + tx];
        tk[ty + r * 8][tx] = Wk[(size_t)(m0 + ty + r * 8) * DD + i0 + tx];
    }
    __syncthreads();
    #pragma unroll
    for (int r = 0; r < 4; r++) {
        g_wqT[(size_t)(i0 + ty + r * 8) * DD + m0 + tx] = __float2bfloat16_rn(tq[tx][ty + r * 8]);
        g_wkT[(size_t)(i0 + ty + r * 8) * DD + m0 + tx] = __float2bfloat16_rn(tk[tx][ty + r * 8]);
    }
}

// x [b][s][d] fp32 -> g_xt [b][d][s] bf16.
// 64(s) x 32(d) tiles; float4 loads, 8B stores with 128B/warp contiguity.
__global__ __launch_bounds__(256) void transpose_kernel(const float* __restrict__ x) {
    __shared__ float tile[64][33];
    int b = blockIdx.z;
    int s0 = blockIdx.x * 64, d0 = blockIdx.y * 32;
    int t = threadIdx.x;
    // load: 64 rows x 8 float4; thread -> row t>>2, float4 cols (t&3), (t&3)+4
    int row = t >> 2, c4 = t & 3;
    const float* src = x + (size_t)b * SS * DD + (size_t)(s0 + row) * DD + d0;
    #pragma unroll
    for (int i = 0; i < 2; i++) {
        int col4 = c4 + 4 * i;
        float4 v = *(const float4*)(src + col4 * 4);
        tile[row][col4 * 4 + 0] = v.x;
        tile[row][col4 * 4 + 1] = v.y;
        tile[row][col4 * 4 + 2] = v.z;
        tile[row][col4 * 4 + 3] = v.w;
    }
    __syncthreads();
    // store: 32 d-rows x 64 s; thread -> d (t>>4) + 16i, s segment (t&15)*4
    int dl = t >> 4, sl = t & 15;
    __nv_bfloat16* dst = g_xt + (size_t)b * DD * SS + s0 + sl * 4;
    #pragma unroll
    for (int i = 0; i < 2; i++) {
        int d = dl + 16 * i;
        __nv_bfloat162 p0 = __floats2bfloat162_rn(tile[sl * 4 + 0][d], tile[sl * 4 + 1][d]);
        __nv_bfloat162 p1 = __floats2bfloat162_rn(tile[sl * 4 + 2][d], tile[sl * 4 + 3][d]);
        uint2 o; o.x = *(u32*)&p0; o.y = *(u32*)&p1;
        *(uint2*)(dst + (size_t)(d0 + d) * SS) = o;
    }
}

// Combine MT split-K partials: g_mt = bf16(sum_z g_mtp[z])
__global__ __launch_bounds__(256) void combine_mt_kernel() {
    const size_t SZ = (size_t)DD * DD;
    int i = blockIdx.x * 256 + threadIdx.x;      // handles 2 elements
    const float2* p0 = (const float2*)g_mtp;
    const float2* p1 = (const float2*)(g_mtp + SZ);
    const float2* p2 = (const float2*)(g_mtp + 2 * SZ);
    const float2* p3 = (const float2*)(g_mtp + 3 * SZ);
    float2 a = p0[i], b = p1[i], c = p2[i], d = p3[i];
    float lo = (a.x + b.x) + (c.x + d.x);
    float hi = (a.y + b.y) + (c.y + d.y);
    *(__nv_bfloat162*)(g_mt + (size_t)i * 2) = __floats2bfloat162_rn(lo, hi);
}

// g_si[row] = 1 / sum_{ntile} g_ps[row][ntile]
__global__ __launch_bounds__(256) void rowsum_kernel() {
    int r = blockIdx.x * 256 + threadIdx.x;
    const float4* ps = (const float4*)(g_ps + (size_t)r * 16);
    float4 a = ps[0], b = ps[1], c = ps[2], d = ps[3];
    float s = (a.x + a.y + a.z + a.w) + (b.x + b.y + b.z + b.w)
            + (c.x + c.y + c.z + c.w) + (d.x + d.y + d.z + d.w);
    g_si[r] = 1.0f / s;
}

// ---------------------------------------------------------------------------
extern "C" void kernel_launch(void* const* d_in, const int* in_sizes, int n_in,
                              void* d_out, int out_size) {
    const float* x    = (const float*)d_in[0];
    const float* ln_g = (const float*)d_in[1];
    const float* ln_b = (const float*)d_in[2];
    const float* Wq   = (const float*)d_in[3];
    const float* bq   = (const float*)d_in[4];
    const float* Wk   = (const float*)d_in[5];
    const float* bk   = (const float*)d_in[6];  (void)bk;
    float* out = (float*)d_out;

    const int SMEM_DYN = NSTAGE * STAGE_BYTES * 2;   // 61440
    cudaFuncSetAttribute(mma_gemm<0>, cudaFuncAttributeMaxDynamicSharedMemorySize, SMEM_DYN);
    cudaFuncSetAttribute(mma_gemm<1>, cudaFuncAttributeMaxDynamicSharedMemorySize, SMEM_DYN);
    cudaFuncSetAttribute(mma_gemm<2>, cudaFuncAttributeMaxDynamicSharedMemorySize, SMEM_DYN);
    cudaFuncSetAttribute(mma_gemm<4>, cudaFuncAttributeMaxDynamicSharedMemorySize, SMEM_DYN);

    __nv_bfloat16 *p_xn, *p_wqT, *p_wkT, *p_mt, *p_g, *p_pb, *p_xt;
    float *p_c, *p_mtp;
    cudaGetSymbolAddress((void**)&p_xn,  g_xn);
    cudaGetSymbolAddress((void**)&p_wqT, g_wqT);
    cudaGetSymbolAddress((void**)&p_wkT, g_wkT);
    cudaGetSymbolAddress((void**)&p_mt,  g_mt);
    cudaGetSymbolAddress((void**)&p_mtp, g_mtp);
    cudaGetSymbolAddress((void**)&p_g,   g_g);
    cudaGetSymbolAddress((void**)&p_pb,  g_pb);
    cudaGetSymbolAddress((void**)&p_xt,  g_xt);
    cudaGetSymbolAddress((void**)&p_c,   g_c);

    w_kernel<<<DD, 256>>>(Wk, bq);
    ln_kernel<<<MTOT, 192>>>(x, ln_g, ln_b);
    convwT_kernel<<<dim3(DD / 32, DD / 32), 256>>>(Wq, Wk);
    transpose_kernel<<<dim3(SS / 64, DD / 32, BB), 256>>>(x);

    // MT[j,i] = sum_m WkT[j,m] * WqT[i,m], split-K x4 -> fp32 partials
    mma_gemm<4><<<dim3(DD / 128, DD / 128, KSPL), 256, SMEM_DYN>>>(
        p_wkT, p_wqT, p_mtp, nullptr, DD, DD, DD / KSPL,
        DD / KSPL, DD / KSPL, (long)DD * DD);
    combine_mt_kernel<<<DD * DD / 512, 256>>>();

    // G = xn @ M   (M=16384, N=768, K=768)
    mma_gemm<0><<<dim3(DD / 128, MTOT / 128, 1), 256, SMEM_DYN>>>(
        p_xn, p_mt, p_g, nullptr, DD, DD, DD, 0, 0, 0);

    // p_unnorm = exp(alpha*(G @ xn^T + c_t)) bf16, + per-row partial sums
    mma_gemm<1><<<dim3(SS / 128, SS / 128, BB), 256, SMEM_DYN>>>(
        p_g, p_xn, p_pb, p_c, SS, DD, DD,
        (long)SS * DD, (long)SS * DD, (long)SS * SS);

    rowsum_kernel<<<MTOT / 256, 256>>>();

    // out = (P_un @ x) * inv_rowsum + x
    mma_gemm<2><<<dim3(DD / 128, SS / 128, BB), 256, SMEM_DYN>>>(
        p_pb, p_xt, out, x, DD, SS, SS,
        (long)SS * SS, (long)DD * SS, (long)SS * DD);
}

// round 16
// speedup vs baseline: 1.5155x; 1.5155x over previous
#include <cuda_runtime.h>
#include <cuda_bf16.h>

#define DD   768
#define BB   8
#define SS   2048
#define MTOT (BB * SS)
#define BK   32
#define PITCH 40                        // bf16 per smem row (80B, conflict-free)
#define STAGE_BYTES (128 * PITCH * 2)   // 10240 per operand tile
#define NSTAGE 3
#define ALPHA 0.036084391824351615f     // 1/sqrt(768)
#define KSPL 4                          // MT GEMM K-splits

typedef unsigned int u32;

// ---------------------------------------------------------------------------
// Device scratch (no allocations allowed)
// ---------------------------------------------------------------------------
__device__ __nv_bfloat16 g_xn [(size_t)MTOT * DD];      // LN output (bf16)
__device__ __nv_bfloat16 g_wqT[(size_t)DD * DD];        // Wq^T bf16 [i][m]
__device__ __nv_bfloat16 g_wkT[(size_t)DD * DD];        // Wk^T bf16 [j][m]
__device__ __nv_bfloat16 g_mt [(size_t)DD * DD];        // M^T bf16, MT[j][i]=M[i][j]
__device__ float         g_mtp[(size_t)KSPL * DD * DD]; // MT split-K fp32 partials
__device__ __nv_bfloat16 g_g  [(size_t)MTOT * DD];      // G = xn @ M  bf16
__device__ __nv_bfloat16 g_pb [(size_t)BB * SS * SS];   // p_unnorm = exp(logit) bf16
__device__ __nv_bfloat16 g_xt [(size_t)BB * DD * SS];   // x^T bf16 [b][d][s]
__device__ float         g_w  [DD];                     // w = Wk^T bq
__device__ float         g_c  [MTOT];                   // c_row = xn_row . w
__device__ float         g_ps [(size_t)MTOT * 16];      // per-(row, ntile) partial sums
__device__ float         g_si [MTOT];                   // 1 / row sum

// ---------------------------------------------------------------------------
__device__ __forceinline__ u32 smem_u32(const void* p) {
    u32 a;
    asm("{ .reg .u64 t; cvta.to.shared.u64 t, %1; cvt.u32.u64 %0, t; }" : "=r"(a) : "l"(p));
    return a;
}
#define CP_ASYNC16(sa, ga) \
    asm volatile("cp.async.cg.shared.global [%0], [%1], 16;" :: "r"(sa), "l"(ga) : "memory")
#define CP_COMMIT()  asm volatile("cp.async.commit_group;" ::: "memory")
#define CP_WAIT(n)   asm volatile("cp.async.wait_group %0;" :: "n"(n) : "memory")
#define LDSM_X4(r0, r1, r2, r3, addr) \
    asm volatile("ldmatrix.sync.aligned.m8n8.x4.shared.b16 {%0,%1,%2,%3}, [%4];" \
        : "=r"(r0), "=r"(r1), "=r"(r2), "=r"(r3) : "r"(addr))

__device__ __forceinline__ void mma16816(float* c, const u32* a, u32 b0, u32 b1) {
    asm volatile(
        "mma.sync.aligned.m16n8k16.row.col.f32.bf16.bf16.f32 "
        "{%0,%1,%2,%3}, {%4,%5,%6,%7}, {%8,%9}, {%0,%1,%2,%3};"
        : "+f"(c[0]), "+f"(c[1]), "+f"(c[2]), "+f"(c[3])
        : "r"(a[0]), "r"(a[1]), "r"(a[2]), "r"(a[3]), "r"(b0), "r"(b1));
}

// ---------------------------------------------------------------------------
// HMMA GEMM (R10-proven shape): C[m,n] = sum_{k<Kloop} A[m,k]*B[n,k]
// 128x128 CTA tile, 256 thr = 8 warps (4m x 2n), warp tile 32x64, BK=32,
// 3-stage cp.async, ldmatrix.x4, 1 sync/iter.
// K = row stride (elements); Kloop = reduction extent (<= K for split-K,
// with aStride/bStride = per-z K-offset).
// MODE 0: bf16 out plain                                         (G)
// MODE 1: p=exp((v+c[col])*ALPHA) bf16 + per-row partial sums    (scores)
// MODE 2: fp32 out: v * g_si[row] + resid                        (av)
// MODE 4: fp32 out plain (split-K partials)                      (MT)
// ---------------------------------------------------------------------------
template <int MODE>
__global__ __launch_bounds__(256) void mma_gemm(
    const __nv_bfloat16* __restrict__ A, const __nv_bfloat16* __restrict__ B,
    void* __restrict__ Cv,
    const float* __restrict__ extra,       // MODE1: c vec (per batch); MODE2: resid
    int N, int K, int Kloop, long aStride, long bStride, long cStride)
{
    extern __shared__ char smem[];
    const u32 aTile0 = smem_u32(smem);
    const u32 bTile0 = aTile0 + NSTAGE * STAGE_BYTES;

    const int tid = threadIdx.x;
    const int wid = tid >> 5, lane = tid & 31;
    const int wm = wid & 3, wn = wid >> 2;          // 4 x 2 warp grid
    const int g = lane >> 2, t = lane & 3;          // mma fragment coords
    const int m0 = blockIdx.y * 128, n0 = blockIdx.x * 128;
    const int z = blockIdx.z;

    A += (size_t)z * aStride + (size_t)m0 * K;
    B += (size_t)z * bStride + (size_t)n0 * K;

    const int NC = Kloop / BK;
    const int r0 = tid >> 2, c0 = (tid & 3) * 8;
    const int r1 = r0 + 64;
    const u32 sA0 = aTile0 + r0 * (PITCH * 2) + c0 * 2;
    const u32 sA1 = aTile0 + r1 * (PITCH * 2) + c0 * 2;
    const u32 sB0 = bTile0 + r0 * (PITCH * 2) + c0 * 2;
    const u32 sB1 = bTile0 + r1 * (PITCH * 2) + c0 * 2;

    const int lr = lane & 15, lk = (lane >> 4) * 8;
    const u32 aLds = aTile0 + (wm * 32 + lr) * (PITCH * 2) + lk * 2;
    const u32 bLds = bTile0 + (wn * 64 + lr) * (PITCH * 2) + lk * 2;

    float acc[2][8][4];
    #pragma unroll
    for (int mt = 0; mt < 2; mt++)
        #pragma unroll
        for (int nt = 0; nt < 8; nt++)
            #pragma unroll
            for (int i = 0; i < 4; i++) acc[mt][nt][i] = 0.f;

    #pragma unroll
    for (int s = 0; s < 2; s++) {
        const __nv_bfloat16* Ak = A + (size_t)s * BK;
        const __nv_bfloat16* Bk = B + (size_t)s * BK;
        const u32 so = s * STAGE_BYTES;
        CP_ASYNC16(sA0 + so, Ak + (size_t)r0 * K + c0);
        CP_ASYNC16(sA1 + so, Ak + (size_t)r1 * K + c0);
        CP_ASYNC16(sB0 + so, Bk + (size_t)r0 * K + c0);
        CP_ASYNC16(sB1 + so, Bk + (size_t)r1 * K + c0);
        CP_COMMIT();
    }

    int st = 0;
    for (int c = 0; c < NC; ++c) {
        CP_WAIT(1);
        __syncthreads();

        if (c + 2 < NC) {
            const int ps = (st + 2 >= NSTAGE) ? st + 2 - NSTAGE : st + 2;
            const __nv_bfloat16* Ak = A + (size_t)(c + 2) * BK;
            const __nv_bfloat16* Bk = B + (size_t)(c + 2) * BK;
            const u32 so = ps * STAGE_BYTES;
            CP_ASYNC16(sA0 + so, Ak + (size_t)r0 * K + c0);
            CP_ASYNC16(sA1 + so, Ak + (size_t)r1 * K + c0);
            CP_ASYNC16(sB0 + so, Bk + (size_t)r0 * K + c0);
            CP_ASYNC16(sB1 + so, Bk + (size_t)r1 * K + c0);
        }
        CP_COMMIT();

        const u32 so = st * STAGE_BYTES;
        #pragma unroll
        for (int kk = 0; kk < 2; kk++) {
            u32 a[2][4], b[4][4];
            #pragma unroll
            for (int mt = 0; mt < 2; mt++)
                LDSM_X4(a[mt][0], a[mt][1], a[mt][2], a[mt][3],
                        aLds + so + mt * (16 * PITCH * 2) + kk * 32);
            #pragma unroll
            for (int np = 0; np < 4; np++)
                LDSM_X4(b[np][0], b[np][1], b[np][2], b[np][3],
                        bLds + so + np * (16 * PITCH * 2) + kk * 32);
            // b[np] = { b_{2np}[0], b_{2np+1}[0], b_{2np}[1], b_{2np+1}[1] }
            #pragma unroll
            for (int mt = 0; mt < 2; mt++)
                #pragma unroll
                for (int nt = 0; nt < 8; nt++)
                    mma16816(acc[mt][nt], a[mt], b[nt >> 1][nt & 1], b[nt >> 1][2 + (nt & 1)]);
        }
        st = (st + 1 >= NSTAGE) ? 0 : st + 1;
    }

    // Epilogue
    if (MODE == 0) {
        #pragma unroll
        for (int mt = 0; mt < 2; mt++)
            #pragma unroll
            for (int nt = 0; nt < 8; nt++) {
                const int row = m0 + wm * 32 + mt * 16 + g;
                const int col = n0 + wn * 64 + nt * 8 + 2 * t;
                __nv_bfloat16* Cb = (__nv_bfloat16*)Cv + (size_t)z * cStride;
                *(__nv_bfloat162*)(Cb + (size_t)row * N + col) =
                    __floats2bfloat162_rn(acc[mt][nt][0], acc[mt][nt][1]);
                *(__nv_bfloat162*)(Cb + (size_t)(row + 8) * N + col) =
                    __floats2bfloat162_rn(acc[mt][nt][2], acc[mt][nt][3]);
            }
    } else if (MODE == 4) {
        #pragma unroll
        for (int mt = 0; mt < 2; mt++)
            #pragma unroll
            for (int nt = 0; nt < 8; nt++) {
                const int row = m0 + wm * 32 + mt * 16 + g;
                const int col = n0 + wn * 64 + nt * 8 + 2 * t;
                float* Cf = (float*)Cv + (size_t)z * cStride;
                *(float2*)(Cf + (size_t)row * N + col) =
                    make_float2(acc[mt][nt][0], acc[mt][nt][1]);
                *(float2*)(Cf + (size_t)(row + 8) * N + col) =
                    make_float2(acc[mt][nt][2], acc[mt][nt][3]);
            }
    } else if (MODE == 1) {
        float rs[2][2] = {{0.f, 0.f}, {0.f, 0.f}};   // [mt][row half]
        const float* cv = extra + (size_t)z * SS;
        #pragma unroll
        for (int mt = 0; mt < 2; mt++)
            #pragma unroll
            for (int nt = 0; nt < 8; nt++) {
                const int row = m0 + wm * 32 + mt * 16 + g;
                const int col = n0 + wn * 64 + nt * 8 + 2 * t;
                float ca = cv[col], cb = cv[col + 1];
                float e0 = __expf((acc[mt][nt][0] + ca) * ALPHA);
                float e1 = __expf((acc[mt][nt][1] + cb) * ALPHA);
                float e2 = __expf((acc[mt][nt][2] + ca) * ALPHA);
                float e3 = __expf((acc[mt][nt][3] + cb) * ALPHA);
                rs[mt][0] += e0 + e1;
                rs[mt][1] += e2 + e3;
                __nv_bfloat16* Cb = (__nv_bfloat16*)Cv + (size_t)z * cStride;
                *(__nv_bfloat162*)(Cb + (size_t)row * N + col) = __floats2bfloat162_rn(e0, e1);
                *(__nv_bfloat162*)(Cb + (size_t)(row + 8) * N + col) = __floats2bfloat162_rn(e2, e3);
            }
        #pragma unroll
        for (int mt = 0; mt < 2; mt++)
            #pragma unroll
            for (int h = 0; h < 2; h++) {
                rs[mt][h] += __shfl_xor_sync(0xffffffffu, rs[mt][h], 1);
                rs[mt][h] += __shfl_xor_sync(0xffffffffu, rs[mt][h], 2);
            }
        __syncthreads();                      // done with mainloop smem; reuse
        float* sRow = (float*)smem;           // [128 rows][2 wn]
        if (t == 0) {
            #pragma unroll
            for (int mt = 0; mt < 2; mt++) {
                sRow[(wm * 32 + mt * 16 + g) * 2 + wn]     = rs[mt][0];
                sRow[(wm * 32 + mt * 16 + 8 + g) * 2 + wn] = rs[mt][1];
            }
        }
        __syncthreads();
        if (tid < 128) {
            float s = sRow[tid * 2] + sRow[tid * 2 + 1];
            g_ps[((size_t)z * SS + m0 + tid) * 16 + blockIdx.x] = s;
        }
    } else {
        float invs[2][2];
        #pragma unroll
        for (int mt = 0; mt < 2; mt++) {
            const int row = m0 + wm * 32 + mt * 16 + g;
            invs[mt][0] = g_si[(size_t)z * SS + row];
            invs[mt][1] = g_si[(size_t)z * SS + row + 8];
        }
        #pragma unroll
        for (int mt = 0; mt < 2; mt++)
            #pragma unroll
            for (int nt = 0; nt < 8; nt++) {
                const int row = m0 + wm * 32 + mt * 16 + g;
                const int col = n0 + wn * 64 + nt * 8 + 2 * t;
                float* Cf = (float*)Cv + (size_t)z * cStride;
                const float* R = extra + (size_t)z * cStride;
                float2 ra = *(const float2*)(R + (size_t)row * N + col);
                float2 rb = *(const float2*)(R + (size_t)(row + 8) * N + col);
                float v0 = acc[mt][nt][0] * invs[mt][0] + ra.x;
                float v1 = acc[mt][nt][1] * invs[mt][0] + ra.y;
                float v2 = acc[mt][nt][2] * invs[mt][1] + rb.x;
                float v3 = acc[mt][nt][3] * invs[mt][1] + rb.y;
                *(float2*)(Cf + (size_t)row * N + col) = make_float2(v0, v1);
                *(float2*)(Cf + (size_t)(row + 8) * N + col) = make_float2(v2, v3);
            }
    }
}

// ---------------------------------------------------------------------------
// Reductions
// ---------------------------------------------------------------------------
__device__ __forceinline__ float blockReduceSum(float v) {
    __shared__ float sh[32];
    int lane = threadIdx.x & 31, wid = threadIdx.x >> 5;
    #pragma unroll
    for (int o = 16; o; o >>= 1) v += __shfl_down_sync(0xffffffffu, v, o);
    if (lane == 0) sh[wid] = v;
    __syncthreads();
    float r = (threadIdx.x < (blockDim.x >> 5)) ? sh[threadIdx.x] : 0.f;
    if (wid == 0) {
        #pragma unroll
        for (int o = 16; o; o >>= 1) r += __shfl_down_sync(0xffffffffu, r, o);
        if (lane == 0) sh[0] = r;
    }
    __syncthreads();
    float out = sh[0];
    __syncthreads();
    return out;
}

// w[d] = sum_j bq[j] * Wk[j,d]
__global__ __launch_bounds__(256) void w_kernel(const float* __restrict__ Wk,
                                                const float* __restrict__ bq) {
    int d = blockIdx.x, t = threadIdx.x;
    float s = 0.f;
    for (int j = t; j < DD; j += 256) s += bq[j] * Wk[(size_t)j * DD + d];
    s = blockReduceSum(s);
    if (t == 0) g_w[d] = s;
}

// LayerNorm -> bf16, plus c_row = xn_row . w
__global__ __launch_bounds__(256) void ln_kernel(const float* __restrict__ x,
                                                 const float* __restrict__ g,
                                                 const float* __restrict__ b) {
    int row = blockIdx.x, t = threadIdx.x;
    const float* xr = x + (size_t)row * DD;
    float v[3];
    #pragma unroll
    for (int i = 0; i < 3; i++) v[i] = xr[t + i * 256];
    float mean = blockReduceSum(v[0] + v[1] + v[2]) * (1.0f / DD);
    float q = 0.f;
    #pragma unroll
    for (int i = 0; i < 3; i++) { float d = v[i] - mean; q += d * d; }
    float inv = rsqrtf(blockReduceSum(q) * (1.0f / DD) + 1e-5f);
    __nv_bfloat16* o = g_xn + (size_t)row * DD;
    float cdot = 0.f;
    #pragma unroll
    for (int i = 0; i < 3; i++) {
        int c = t + i * 256;
        float xv = (v[i] - mean) * inv * g[c] + b[c];
        o[c] = __float2bfloat16_rn(xv);
        cdot += xv * g_w[c];
    }
    cdot = blockReduceSum(cdot);
    if (t == 0) g_c[row] = cdot;
}

// Transpose W fp32 [m][i] -> bf16 [i][m] for both weights
__global__ __launch_bounds__(256) void convwT_kernel(const float* __restrict__ Wq,
                                                     const float* __restrict__ Wk) {
    __shared__ float tq[32][33];
    __shared__ float tk[32][33];
    int m0 = blockIdx.x * 32, i0 = blockIdx.y * 32;
    int tx = threadIdx.x & 31, ty = threadIdx.x >> 5;
    #pragma unroll
    for (int r = 0; r < 4; r++) {
        tq[ty + r * 8][tx] = Wq[(size_t)(m0 + ty + r * 8) * DD + i0 + tx];
        tk[ty + r * 8][tx] = Wk[(size_t)(m0 + ty + r * 8) * DD + i0 + tx];
    }
    __syncthreads();
    #pragma unroll
    for (int r = 0; r < 4; r++) {
        g_wqT[(size_t)(i0 + ty + r * 8) * DD + m0 + tx] = __float2bfloat16_rn(tq[tx][ty + r * 8]);
        g_wkT[(size_t)(i0 + ty + r * 8) * DD + m0 + tx] = __float2bfloat16_rn(tk[tx][ty + r * 8]);
    }
}

// x [b][s][d] fp32 -> g_xt [b][d][s] bf16 (R8-proven scalar version)
__global__ __launch_bounds__(256) void transpose_kernel(const float* __restrict__ x) {
    __shared__ float t[32][33];
    int b = blockIdx.z;
    int s0 = blockIdx.x * 32, d0 = blockIdx.y * 32;
    int tx = threadIdx.x & 31, ty = threadIdx.x >> 5;
    #pragma unroll
    for (int i = 0; i < 4; i++)
        t[ty + i * 8][tx] = x[(size_t)b * SS * DD + (size_t)(s0 + ty + i * 8) * DD + d0 + tx];
    __syncthreads();
    #pragma unroll
    for (int i = 0; i < 4; i++)
        g_xt[(size_t)b * DD * SS + (size_t)(d0 + ty + i * 8) * SS + s0 + tx] =
            __float2bfloat16_rn(t[tx][ty + i * 8]);
}

// Combine MT split-K partials: g_mt = bf16(sum_z g_mtp[z])
__global__ __launch_bounds__(256) void combine_mt_kernel() {
    const size_t SZ = (size_t)DD * DD;
    int i = blockIdx.x * 256 + threadIdx.x;      // handles 2 elements
    const float2* p0 = (const float2*)g_mtp;
    const float2* p1 = (const float2*)(g_mtp + SZ);
    const float2* p2 = (const float2*)(g_mtp + 2 * SZ);
    const float2* p3 = (const float2*)(g_mtp + 3 * SZ);
    float2 a = p0[i], b = p1[i], c = p2[i], d = p3[i];
    float lo = (a.x + b.x) + (c.x + d.x);
    float hi = (a.y + b.y) + (c.y + d.y);
    *(__nv_bfloat162*)(g_mt + (size_t)i * 2) = __floats2bfloat162_rn(lo, hi);
}

// g_si[row] = 1 / sum_{ntile} g_ps[row][ntile]
__global__ __launch_bounds__(256) void rowsum_kernel() {
    int r = blockIdx.x * 256 + threadIdx.x;
    const float4* ps = (const float4*)(g_ps + (size_t)r * 16);
    float4 a = ps[0], b = ps[1], c = ps[2], d = ps[3];
    float s = (a.x + a.y + a.z + a.w) + (b.x + b.y + b.z + b.w)
            + (c.x + c.y + c.z + c.w) + (d.x + d.y + d.z + d.w);
    g_si[r] = 1.0f / s;
}

// ---------------------------------------------------------------------------
extern "C" void kernel_launch(void* const* d_in, const int* in_sizes, int n_in,
                              void* d_out, int out_size) {
    const float* x    = (const float*)d_in[0];
    const float* ln_g = (const float*)d_in[1];
    const float* ln_b = (const float*)d_in[2];
    const float* Wq   = (const float*)d_in[3];
    const float* bq   = (const float*)d_in[4];
    const float* Wk   = (const float*)d_in[5];
    const float* bk   = (const float*)d_in[6];  (void)bk;
    float* out = (float*)d_out;

    const int SMEM_DYN = NSTAGE * STAGE_BYTES * 2;   // 61440
    cudaFuncSetAttribute(mma_gemm<0>, cudaFuncAttributeMaxDynamicSharedMemorySize, SMEM_DYN);
    cudaFuncSetAttribute(mma_gemm<1>, cudaFuncAttributeMaxDynamicSharedMemorySize, SMEM_DYN);
    cudaFuncSetAttribute(mma_gemm<2>, cudaFuncAttributeMaxDynamicSharedMemorySize, SMEM_DYN);
    cudaFuncSetAttribute(mma_gemm<4>, cudaFuncAttributeMaxDynamicSharedMemorySize, SMEM_DYN);

    __nv_bfloat16 *p_xn, *p_wqT, *p_wkT, *p_mt, *p_g, *p_pb, *p_xt;
    float *p_c, *p_mtp;
    cudaGetSymbolAddress((void**)&p_xn,  g_xn);
    cudaGetSymbolAddress((void**)&p_wqT, g_wqT);
    cudaGetSymbolAddress((void**)&p_wkT, g_wkT);
    cudaGetSymbolAddress((void**)&p_mt,  g_mt);
    cudaGetSymbolAddress((void**)&p_mtp, g_mtp);
    cudaGetSymbolAddress((void**)&p_g,   g_g);
    cudaGetSymbolAddress((void**)&p_pb,  g_pb);
    cudaGetSymbolAddress((void**)&p_xt,  g_xt);
    cudaGetSymbolAddress((void**)&p_c,   g_c);

    w_kernel<<<DD, 256>>>(Wk, bq);
    ln_kernel<<<MTOT, 256>>>(x, ln_g, ln_b);
    convwT_kernel<<<dim3(DD / 32, DD / 32), 256>>>(Wq, Wk);
    transpose_kernel<<<dim3(SS / 32, DD / 32, BB), 256>>>(x);

    // MT[j,i] = sum_m WkT[j,m] * WqT[i,m], split-K x4 -> fp32 partials
    mma_gemm<4><<<dim3(DD / 128, DD / 128, KSPL), 256, SMEM_DYN>>>(
        p_wkT, p_wqT, p_mtp, nullptr, DD, DD, DD / KSPL,
        DD / KSPL, DD / KSPL, (long)DD * DD);
    combine_mt_kernel<<<DD * DD / 512, 256>>>();

    // G = xn @ M   (M=16384, N=768, K=768)
    mma_gemm<0><<<dim3(DD / 128, MTOT / 128, 1), 256, SMEM_DYN>>>(
        p_xn, p_mt, p_g, nullptr, DD, DD, DD, 0, 0, 0);

    // p_unnorm = exp(alpha*(G @ xn^T + c_t)) bf16, + per-row partial sums
    mma_gemm<1><<<dim3(SS / 128, SS / 128, BB), 256, SMEM_DYN>>>(
        p_g, p_xn, p_pb, p_c, SS, DD, DD,
        (long)SS * DD, (long)SS * DD, (long)SS * SS);

    rowsum_kernel<<<MTOT / 256, 256>>>();

    // out = (P_un @ x) * inv_rowsum + x
    mma_gemm<2><<<dim3(DD / 128, SS / 128, BB), 256, SMEM_DYN>>>(
        p_pb, p_xt, out, x, DD, SS, SS,
        (long)SS * SS, (long)DD * SS, (long)SS * DD);
}

// round 17
// speedup vs baseline: 1.5165x; 1.0006x over previous
#include <cuda_runtime.h>
#include <cuda_bf16.h>

#define DD   768
#define BB   8
#define SS   2048
#define MTOT (BB * SS)
#define BK   32
#define PITCH 40                        // bf16 per smem row (80B, conflict-free)
#define STAGE_BYTES (128 * PITCH * 2)   // 10240 per operand tile
#define NSTAGE 3
#define ALPHA 0.036084391824351615f     // 1/sqrt(768)
#define KSPL 4                          // MT GEMM K-splits

typedef unsigned int u32;

// ---------------------------------------------------------------------------
// Device scratch (no allocations allowed)
// ---------------------------------------------------------------------------
__device__ __nv_bfloat16 g_xn [(size_t)MTOT * DD];      // LN output (bf16)
__device__ __nv_bfloat16 g_wqT[(size_t)DD * DD];        // Wq^T bf16 [i][m]
__device__ __nv_bfloat16 g_wkT[(size_t)DD * DD];        // Wk^T bf16 [j][m]
__device__ __nv_bfloat16 g_mt [(size_t)DD * DD];        // M^T bf16, MT[j][i]=M[i][j]
__device__ float         g_mtp[(size_t)KSPL * DD * DD]; // MT split-K fp32 partials
__device__ __nv_bfloat16 g_g  [(size_t)MTOT * DD];      // G = xn @ M  bf16
__device__ __nv_bfloat16 g_pb [(size_t)BB * SS * SS];   // p_unnorm = exp(logit) bf16
__device__ __nv_bfloat16 g_xt [(size_t)BB * DD * SS];   // x^T bf16 [b][d][s]
__device__ float         g_w  [DD];                     // w = Wk^T bq
__device__ float         g_c  [MTOT];                   // c_row = xn_row . w
__device__ float         g_ps [(size_t)MTOT * 16];      // per-(row, ntile) partial sums

// ---------------------------------------------------------------------------
__device__ __forceinline__ u32 smem_u32(const void* p) {
    u32 a;
    asm("{ .reg .u64 t; cvta.to.shared.u64 t, %1; cvt.u32.u64 %0, t; }" : "=r"(a) : "l"(p));
    return a;
}
#define CP_ASYNC16(sa, ga) \
    asm volatile("cp.async.cg.shared.global [%0], [%1], 16;" :: "r"(sa), "l"(ga) : "memory")
#define CP_COMMIT()  asm volatile("cp.async.commit_group;" ::: "memory")
#define CP_WAIT(n)   asm volatile("cp.async.wait_group %0;" :: "n"(n) : "memory")
#define LDSM_X4(r0, r1, r2, r3, addr) \
    asm volatile("ldmatrix.sync.aligned.m8n8.x4.shared.b16 {%0,%1,%2,%3}, [%4];" \
        : "=r"(r0), "=r"(r1), "=r"(r2), "=r"(r3) : "r"(addr))

__device__ __forceinline__ void mma16816(float* c, const u32* a, u32 b0, u32 b1) {
    asm volatile(
        "mma.sync.aligned.m16n8k16.row.col.f32.bf16.bf16.f32 "
        "{%0,%1,%2,%3}, {%4,%5,%6,%7}, {%8,%9}, {%0,%1,%2,%3};"
        : "+f"(c[0]), "+f"(c[1]), "+f"(c[2]), "+f"(c[3])
        : "r"(a[0]), "r"(a[1]), "r"(a[2]), "r"(a[3]), "r"(b0), "r"(b1));
}

// ---------------------------------------------------------------------------
// HMMA GEMM (R10-proven shape): C[m,n] = sum_{k<Kloop} A[m,k]*B[n,k]
// 128x128 CTA tile, 256 thr = 8 warps (4m x 2n), warp tile 32x64, BK=32,
// 3-stage cp.async, ldmatrix.x4, 1 sync/iter.
// K = row stride (elements); Kloop = reduction extent (<= K for split-K,
// with aStride/bStride = per-z K-offset).
// MODE 0: bf16 out plain                                         (G)
// MODE 1: p=exp((v+c[col])*ALPHA) bf16 + per-row partial sums    (scores)
// MODE 2: fp32 out: v * invRowSum + resid (invsum fused in-smem) (av)
// MODE 4: fp32 out plain (split-K partials)                      (MT)
// ---------------------------------------------------------------------------
template <int MODE>
__global__ __launch_bounds__(256) void mma_gemm(
    const __nv_bfloat16* __restrict__ A, const __nv_bfloat16* __restrict__ B,
    void* __restrict__ Cv,
    const float* __restrict__ extra,       // MODE1: c vec (per batch); MODE2: resid
    int N, int K, int Kloop, long aStride, long bStride, long cStride)
{
    extern __shared__ char smem[];
    const u32 aTile0 = smem_u32(smem);
    const u32 bTile0 = aTile0 + NSTAGE * STAGE_BYTES;
    float* sInv = (float*)(smem + 2 * NSTAGE * STAGE_BYTES);   // 128 floats (MODE 2)

    const int tid = threadIdx.x;
    const int wid = tid >> 5, lane = tid & 31;
    const int wm = wid & 3, wn = wid >> 2;          // 4 x 2 warp grid
    const int g = lane >> 2, t = lane & 3;          // mma fragment coords
    const int m0 = blockIdx.y * 128, n0 = blockIdx.x * 128;
    const int z = blockIdx.z;

    A += (size_t)z * aStride + (size_t)m0 * K;
    B += (size_t)z * bStride + (size_t)n0 * K;

    const int NC = Kloop / BK;
    const int r0 = tid >> 2, c0 = (tid & 3) * 8;
    const int r1 = r0 + 64;
    const u32 sA0 = aTile0 + r0 * (PITCH * 2) + c0 * 2;
    const u32 sA1 = aTile0 + r1 * (PITCH * 2) + c0 * 2;
    const u32 sB0 = bTile0 + r0 * (PITCH * 2) + c0 * 2;
    const u32 sB1 = bTile0 + r1 * (PITCH * 2) + c0 * 2;

    const int lr = lane & 15, lk = (lane >> 4) * 8;
    const u32 aLds = aTile0 + (wm * 32 + lr) * (PITCH * 2) + lk * 2;
    const u32 bLds = bTile0 + (wn * 64 + lr) * (PITCH * 2) + lk * 2;

    float acc[2][8][4];
    #pragma unroll
    for (int mt = 0; mt < 2; mt++)
        #pragma unroll
        for (int nt = 0; nt < 8; nt++)
            #pragma unroll
            for (int i = 0; i < 4; i++) acc[mt][nt][i] = 0.f;

    #pragma unroll
    for (int s = 0; s < 2; s++) {
        const __nv_bfloat16* Ak = A + (size_t)s * BK;
        const __nv_bfloat16* Bk = B + (size_t)s * BK;
        const u32 so = s * STAGE_BYTES;
        CP_ASYNC16(sA0 + so, Ak + (size_t)r0 * K + c0);
        CP_ASYNC16(sA1 + so, Ak + (size_t)r1 * K + c0);
        CP_ASYNC16(sB0 + so, Bk + (size_t)r0 * K + c0);
        CP_ASYNC16(sB1 + so, Bk + (size_t)r1 * K + c0);
        CP_COMMIT();
    }

    // MODE 2: fused inverse row sums — hidden under the pipeline prologue.
    // Ordered before epilogue reads by the mainloop's __syncthreads.
    if (MODE == 2 && tid < 128) {
        const float4* ps = (const float4*)(g_ps + ((size_t)z * SS + m0 + tid) * 16);
        float4 a = ps[0], b = ps[1], c = ps[2], d = ps[3];
        float s = (a.x + a.y + a.z + a.w) + (b.x + b.y + b.z + b.w)
                + (c.x + c.y + c.z + c.w) + (d.x + d.y + d.z + d.w);
        sInv[tid] = 1.0f / s;
    }

    int st = 0;
    for (int c = 0; c < NC; ++c) {
        CP_WAIT(1);
        __syncthreads();

        if (c + 2 < NC) {
            const int ps = (st + 2 >= NSTAGE) ? st + 2 - NSTAGE : st + 2;
            const __nv_bfloat16* Ak = A + (size_t)(c + 2) * BK;
            const __nv_bfloat16* Bk = B + (size_t)(c + 2) * BK;
            const u32 so = ps * STAGE_BYTES;
            CP_ASYNC16(sA0 + so, Ak + (size_t)r0 * K + c0);
            CP_ASYNC16(sA1 + so, Ak + (size_t)r1 * K + c0);
            CP_ASYNC16(sB0 + so, Bk + (size_t)r0 * K + c0);
            CP_ASYNC16(sB1 + so, Bk + (size_t)r1 * K + c0);
        }
        CP_COMMIT();

        const u32 so = st * STAGE_BYTES;
        #pragma unroll
        for (int kk = 0; kk < 2; kk++) {
            u32 a[2][4], b[4][4];
            #pragma unroll
            for (int mt = 0; mt < 2; mt++)
                LDSM_X4(a[mt][0], a[mt][1], a[mt][2], a[mt][3],
                        aLds + so + mt * (16 * PITCH * 2) + kk * 32);
            #pragma unroll
            for (int np = 0; np < 4; np++)
                LDSM_X4(b[np][0], b[np][1], b[np][2], b[np][3],
                        bLds + so + np * (16 * PITCH * 2) + kk * 32);
            // b[np] = { b_{2np}[0], b_{2np+1}[0], b_{2np}[1], b_{2np+1}[1] }
            #pragma unroll
            for (int mt = 0; mt < 2; mt++)
                #pragma unroll
                for (int nt = 0; nt < 8; nt++)
                    mma16816(acc[mt][nt], a[mt], b[nt >> 1][nt & 1], b[nt >> 1][2 + (nt & 1)]);
        }
        st = (st + 1 >= NSTAGE) ? 0 : st + 1;
    }

    // Epilogue
    if (MODE == 0) {
        #pragma unroll
        for (int mt = 0; mt < 2; mt++)
            #pragma unroll
            for (int nt = 0; nt < 8; nt++) {
                const int row = m0 + wm * 32 + mt * 16 + g;
                const int col = n0 + wn * 64 + nt * 8 + 2 * t;
                __nv_bfloat16* Cb = (__nv_bfloat16*)Cv + (size_t)z * cStride;
                *(__nv_bfloat162*)(Cb + (size_t)row * N + col) =
                    __floats2bfloat162_rn(acc[mt][nt][0], acc[mt][nt][1]);
                *(__nv_bfloat162*)(Cb + (size_t)(row + 8) * N + col) =
                    __floats2bfloat162_rn(acc[mt][nt][2], acc[mt][nt][3]);
            }
    } else if (MODE == 4) {
        #pragma unroll
        for (int mt = 0; mt < 2; mt++)
            #pragma unroll
            for (int nt = 0; nt < 8; nt++) {
                const int row = m0 + wm * 32 + mt * 16 + g;
                const int col = n0 + wn * 64 + nt * 8 + 2 * t;
                float* Cf = (float*)Cv + (size_t)z * cStride;
                *(float2*)(Cf + (size_t)row * N + col) =
                    make_float2(acc[mt][nt][0], acc[mt][nt][1]);
                *(float2*)(Cf + (size_t)(row + 8) * N + col) =
                    make_float2(acc[mt][nt][2], acc[mt][nt][3]);
            }
    } else if (MODE == 1) {
        float rs[2][2] = {{0.f, 0.f}, {0.f, 0.f}};   // [mt][row half]
        const float* cv = extra + (size_t)z * SS;
        #pragma unroll
        for (int mt = 0; mt < 2; mt++)
            #pragma unroll
            for (int nt = 0; nt < 8; nt++) {
                const int row = m0 + wm * 32 + mt * 16 + g;
                const int col = n0 + wn * 64 + nt * 8 + 2 * t;
                float ca = cv[col], cb = cv[col + 1];
                float e0 = __expf((acc[mt][nt][0] + ca) * ALPHA);
                float e1 = __expf((acc[mt][nt][1] + cb) * ALPHA);
                float e2 = __expf((acc[mt][nt][2] + ca) * ALPHA);
                float e3 = __expf((acc[mt][nt][3] + cb) * ALPHA);
                rs[mt][0] += e0 + e1;
                rs[mt][1] += e2 + e3;
                __nv_bfloat16* Cb = (__nv_bfloat16*)Cv + (size_t)z * cStride;
                *(__nv_bfloat162*)(Cb + (size_t)row * N + col) = __floats2bfloat162_rn(e0, e1);
                *(__nv_bfloat162*)(Cb + (size_t)(row + 8) * N + col) = __floats2bfloat162_rn(e2, e3);
            }
        #pragma unroll
        for (int mt = 0; mt < 2; mt++)
            #pragma unroll
            for (int h = 0; h < 2; h++) {
                rs[mt][h] += __shfl_xor_sync(0xffffffffu, rs[mt][h], 1);
                rs[mt][h] += __shfl_xor_sync(0xffffffffu, rs[mt][h], 2);
            }
        __syncthreads();                      // done with mainloop smem; reuse
        float* sRow = (float*)smem;           // [128 rows][2 wn]
        if (t == 0) {
            #pragma unroll
            for (int mt = 0; mt < 2; mt++) {
                sRow[(wm * 32 + mt * 16 + g) * 2 + wn]     = rs[mt][0];
                sRow[(wm * 32 + mt * 16 + 8 + g) * 2 + wn] = rs[mt][1];
            }
        }
        __syncthreads();
        if (tid < 128) {
            float s = sRow[tid * 2] + sRow[tid * 2 + 1];
            g_ps[((size_t)z * SS + m0 + tid) * 16 + blockIdx.x] = s;
        }
    } else {
        float invs[2][2];
        #pragma unroll
        for (int mt = 0; mt < 2; mt++) {
            const int rl = wm * 32 + mt * 16 + g;
            invs[mt][0] = sInv[rl];
            invs[mt][1] = sInv[rl + 8];
        }
        #pragma unroll
        for (int mt = 0; mt < 2; mt++)
            #pragma unroll
            for (int nt = 0; nt < 8; nt++) {
                const int row = m0 + wm * 32 + mt * 16 + g;
                const int col = n0 + wn * 64 + nt * 8 + 2 * t;
                float* Cf = (float*)Cv + (size_t)z * cStride;
                const float* R = extra + (size_t)z * cStride;
                float2 ra = *(const float2*)(R + (size_t)row * N + col);
                float2 rb = *(const float2*)(R + (size_t)(row + 8) * N + col);
                float v0 = acc[mt][nt][0] * invs[mt][0] + ra.x;
                float v1 = acc[mt][nt][1] * invs[mt][0] + ra.y;
                float v2 = acc[mt][nt][2] * invs[mt][1] + rb.x;
                float v3 = acc[mt][nt][3] * invs[mt][1] + rb.y;
                *(float2*)(Cf + (size_t)row * N + col) = make_float2(v0, v1);
                *(float2*)(Cf + (size_t)(row + 8) * N + col) = make_float2(v2, v3);
            }
    }
}

// ---------------------------------------------------------------------------
// Reductions
// ---------------------------------------------------------------------------
__device__ __forceinline__ float blockReduceSum(float v) {
    __shared__ float sh[32];
    int lane = threadIdx.x & 31, wid = threadIdx.x >> 5;
    #pragma unroll
    for (int o = 16; o; o >>= 1) v += __shfl_down_sync(0xffffffffu, v, o);
    if (lane == 0) sh[wid] = v;
    __syncthreads();
    float r = (threadIdx.x < (blockDim.x >> 5)) ? sh[threadIdx.x] : 0.f;
    if (wid == 0) {
        #pragma unroll
        for (int o = 16; o; o >>= 1) r += __shfl_down_sync(0xffffffffu, r, o);
        if (lane == 0) sh[0] = r;
    }
    __syncthreads();
    float out = sh[0];
    __syncthreads();
    return out;
}

// w[d] = sum_j bq[j] * Wk[j,d]
__global__ __launch_bounds__(256) void w_kernel(const float* __restrict__ Wk,
                                                const float* __restrict__ bq) {
    int d = blockIdx.x, t = threadIdx.x;
    float s = 0.f;
    for (int j = t; j < DD; j += 256) s += bq[j] * Wk[(size_t)j * DD + d];
    s = blockReduceSum(s);
    if (t == 0) g_w[d] = s;
}

// LayerNorm -> bf16, plus c_row = xn_row . w
__global__ __launch_bounds__(256) void ln_kernel(const float* __restrict__ x,
                                                 const float* __restrict__ g,
                                                 const float* __restrict__ b) {
    int row = blockIdx.x, t = threadIdx.x;
    const float* xr = x + (size_t)row * DD;
    float v[3];
    #pragma unroll
    for (int i = 0; i < 3; i++) v[i] = xr[t + i * 256];
    float mean = blockReduceSum(v[0] + v[1] + v[2]) * (1.0f / DD);
    float q = 0.f;
    #pragma unroll
    for (int i = 0; i < 3; i++) { float d = v[i] - mean; q += d * d; }
    float inv = rsqrtf(blockReduceSum(q) * (1.0f / DD) + 1e-5f);
    __nv_bfloat16* o = g_xn + (size_t)row * DD;
    float cdot = 0.f;
    #pragma unroll
    for (int i = 0; i < 3; i++) {
        int c = t + i * 256;
        float xv = (v[i] - mean) * inv * g[c] + b[c];
        o[c] = __float2bfloat16_rn(xv);
        cdot += xv * g_w[c];
    }
    cdot = blockReduceSum(cdot);
    if (t == 0) g_c[row] = cdot;
}

// Transpose W fp32 [m][i] -> bf16 [i][m] for both weights
__global__ __launch_bounds__(256) void convwT_kernel(const float* __restrict__ Wq,
                                                     const float* __restrict__ Wk) {
    __shared__ float tq[32][33];
    __shared__ float tk[32][33];
    int m0 = blockIdx.x * 32, i0 = blockIdx.y * 32;
    int tx = threadIdx.x & 31, ty = threadIdx.x >> 5;
    #pragma unroll
    for (int r = 0; r < 4; r++) {
        tq[ty + r * 8][tx] = Wq[(size_t)(m0 + ty + r * 8) * DD + i0 + tx];
        tk[ty + r * 8][tx] = Wk[(size_t)(m0 + ty + r * 8) * DD + i0 + tx];
    }
    __syncthreads();
    #pragma unroll
    for (int r = 0; r < 4; r++) {
        g_wqT[(size_t)(i0 + ty + r * 8) * DD + m0 + tx] = __float2bfloat16_rn(tq[tx][ty + r * 8]);
        g_wkT[(size_t)(i0 + ty + r * 8) * DD + m0 + tx] = __float2bfloat16_rn(tk[tx][ty + r * 8]);
    }
}

// x [b][s][d] fp32 -> g_xt [b][d][s] bf16 (R8-proven scalar version)
__global__ __launch_bounds__(256) void transpose_kernel(const float* __restrict__ x) {
    __shared__ float t[32][33];
    int b = blockIdx.z;
    int s0 = blockIdx.x * 32, d0 = blockIdx.y * 32;
    int tx = threadIdx.x & 31, ty = threadIdx.x >> 5;
    #pragma unroll
    for (int i = 0; i < 4; i++)
        t[ty + i * 8][tx] = x[(size_t)b * SS * DD + (size_t)(s0 + ty + i * 8) * DD + d0 + tx];
    __syncthreads();
    #pragma unroll
    for (int i = 0; i < 4; i++)
        g_xt[(size_t)b * DD * SS + (size_t)(d0 + ty + i * 8) * SS + s0 + tx] =
            __float2bfloat16_rn(t[tx][ty + i * 8]);
}

// Combine MT split-K partials: g_mt = bf16(sum_z g_mtp[z])
__global__ __launch_bounds__(256) void combine_mt_kernel() {
    const size_t SZ = (size_t)DD * DD;
    int i = blockIdx.x * 256 + threadIdx.x;      // handles 2 elements
    const float2* p0 = (const float2*)g_mtp;
    const float2* p1 = (const float2*)(g_mtp + SZ);
    const float2* p2 = (const float2*)(g_mtp + 2 * SZ);
    const float2* p3 = (const float2*)(g_mtp + 3 * SZ);
    float2 a = p0[i], b = p1[i], c = p2[i], d = p3[i];
    float lo = (a.x + b.x) + (c.x + d.x);
    float hi = (a.y + b.y) + (c.y + d.y);
    *(__nv_bfloat162*)(g_mt + (size_t)i * 2) = __floats2bfloat162_rn(lo, hi);
}

// ---------------------------------------------------------------------------
extern "C" void kernel_launch(void* const* d_in, const int* in_sizes, int n_in,
                              void* d_out, int out_size) {
    const float* x    = (const float*)d_in[0];
    const float* ln_g = (const float*)d_in[1];
    const float* ln_b = (const float*)d_in[2];
    const float* Wq   = (const float*)d_in[3];
    const float* bq   = (const float*)d_in[4];
    const float* Wk   = (const float*)d_in[5];
    const float* bk   = (const float*)d_in[6];  (void)bk;
    float* out = (float*)d_out;

    const int SMEM_DYN = NSTAGE * STAGE_BYTES * 2 + 512;   // tiles + sInv stash
    cudaFuncSetAttribute(mma_gemm<0>, cudaFuncAttributeMaxDynamicSharedMemorySize, SMEM_DYN);
    cudaFuncSetAttribute(mma_gemm<1>, cudaFuncAttributeMaxDynamicSharedMemorySize, SMEM_DYN);
    cudaFuncSetAttribute(mma_gemm<2>, cudaFuncAttributeMaxDynamicSharedMemorySize, SMEM_DYN);
    cudaFuncSetAttribute(mma_gemm<4>, cudaFuncAttributeMaxDynamicSharedMemorySize, SMEM_DYN);

    __nv_bfloat16 *p_xn, *p_wqT, *p_wkT, *p_mt, *p_g, *p_pb, *p_xt;
    float *p_c, *p_mtp;
    cudaGetSymbolAddress((void**)&p_xn,  g_xn);
    cudaGetSymbolAddress((void**)&p_wqT, g_wqT);
    cudaGetSymbolAddress((void**)&p_wkT, g_wkT);
    cudaGetSymbolAddress((void**)&p_mt,  g_mt);
    cudaGetSymbolAddress((void**)&p_mtp, g_mtp);
    cudaGetSymbolAddress((void**)&p_g,   g_g);
    cudaGetSymbolAddress((void**)&p_pb,  g_pb);
    cudaGetSymbolAddress((void**)&p_xt,  g_xt);
    cudaGetSymbolAddress((void**)&p_c,   g_c);

    w_kernel<<<DD, 256>>>(Wk, bq);
    ln_kernel<<<MTOT, 256>>>(x, ln_g, ln_b);
    convwT_kernel<<<dim3(DD / 32, DD / 32), 256>>>(Wq, Wk);
    transpose_kernel<<<dim3(SS / 32, DD / 32, BB), 256>>>(x);

    // MT[j,i] = sum_m WkT[j,m] * WqT[i,m], split-K x4 -> fp32 partials
    mma_gemm<4><<<dim3(DD / 128, DD / 128, KSPL), 256, SMEM_DYN>>>(
        p_wkT, p_wqT, p_mtp, nullptr, DD, DD, DD / KSPL,
        DD / KSPL, DD / KSPL, (long)DD * DD);
    combine_mt_kernel<<<DD * DD / 512, 256>>>();

    // G = xn @ M   (M=16384, N=768, K=768)
    mma_gemm<0><<<dim3(DD / 128, MTOT / 128, 1), 256, SMEM_DYN>>>(
        p_xn, p_mt, p_g, nullptr, DD, DD, DD, 0, 0, 0);

    // p_unnorm = exp(alpha*(G @ xn^T + c_t)) bf16, + per-row partial sums
    mma_gemm<1><<<dim3(SS / 128, SS / 128, BB), 256, SMEM_DYN>>>(
        p_g, p_xn, p_pb, p_c, SS, DD, DD,
        (long)SS * DD, (long)SS * DD, (long)SS * SS);

    // out = (P_un @ x) * inv_rowsum + x   (row sums fused from g_ps in-kernel)
    mma_gemm<2><<<dim3(DD / 128, SS / 128, BB), 256, SMEM_DYN>>>(
        p_pb, p_xt, out, x, DD, SS, SS,
        (long)SS * SS, (long)DD * SS, (long)SS * DD);
}